// round 6
// baseline (speedup 1.0000x reference)
#include <cuda_runtime.h>
#include <mma.h>

using namespace nvcuda;

#define EDIM   2048
#define NHEADS 16
#define DHEAD  128
#define NBATCH 4
#define SEQ    2048
#define MROWS  (NBATCH * SEQ)   // 8192

// ---------------- scratch (no allocs allowed) ----------------
__device__ float g_q[16777216];   // (N*H, S, D)
__device__ float g_k[16777216];
__device__ float g_v[16777216];
__device__ float g_o[16777216];   // (N*S, E)

// ---------------- cp.async helpers ----------------
__device__ __forceinline__ void cp_async16(void* smem, const void* gmem) {
    unsigned saddr = (unsigned)__cvta_generic_to_shared(smem);
    asm volatile("cp.async.cg.shared.global [%0], [%1], 16;\n" :: "r"(saddr), "l"(gmem));
}
__device__ __forceinline__ void cp_commit() {
    asm volatile("cp.async.commit_group;\n");
}
template <int N>
__device__ __forceinline__ void cp_wait() {
    asm volatile("cp.async.wait_group %0;\n" :: "n"(N));
}

// =================================================================
// TF32 GEMM:  C[M=8192, N=2048] = A[M,E] @ W[N,E]^T   (no bias)
// 128x128 block tile, BK=32, 4 warps (64x64 each), double-buffered cp.async
// permuted=1 -> write C to (batch, head, s, d) layout for attention
// =================================================================
#define GLDA 40   // 32 + 8 pad (floats); 160B rows, 16B aligned
#define GEMM_SMEM (4 * 128 * GLDA * 4)  // 81920 B

__device__ __forceinline__ void gemm_load_stage(
    float* As, float* Bs, const float* A, const float* W,
    int m0, int n0, int k0, int tid)
{
#pragma unroll
    for (int i = 0; i < 8; i++) {
        int id = tid + i * 128;
        int r = id >> 3, c = (id & 7) << 2;
        cp_async16(As + r * GLDA + c, A + (size_t)(m0 + r) * EDIM + k0 + c);
    }
#pragma unroll
    for (int i = 0; i < 8; i++) {
        int id = tid + i * 128;
        int r = id >> 3, c = (id & 7) << 2;
        cp_async16(Bs + r * GLDA + c, W + (size_t)(n0 + r) * EDIM + k0 + c);
    }
}

__global__ __launch_bounds__(128) void gemm_at_kernel(
    const float* __restrict__ A, const float* __restrict__ W,
    float* __restrict__ out, int permuted)
{
    extern __shared__ float sg[];
    float* Asb[2] = { sg,                sg + 128 * GLDA };
    float* Bsb[2] = { sg + 2*128*GLDA,   sg + 3*128*GLDA };

    const int tid  = threadIdx.x;
    const int warp = tid >> 5;
    const int m0 = blockIdx.y * 128;
    const int n0 = blockIdx.x * 128;
    const int wr = warp >> 1;   // 0..1
    const int wc = warp & 1;    // 0..1

    wmma::fragment<wmma::accumulator, 16, 16, 8, float> acc[4][4];
#pragma unroll
    for (int i = 0; i < 4; i++)
#pragma unroll
        for (int j = 0; j < 4; j++)
            wmma::fill_fragment(acc[i][j], 0.0f);

    gemm_load_stage(Asb[0], Bsb[0], A, W, m0, n0, 0, tid);
    cp_commit();

    for (int k0 = 0; k0 < EDIM; k0 += 32) {
        const int buf = (k0 >> 5) & 1;
        if (k0 + 32 < EDIM) {
            gemm_load_stage(Asb[buf ^ 1], Bsb[buf ^ 1], A, W, m0, n0, k0 + 32, tid);
            cp_commit();
            cp_wait<1>();
        } else {
            cp_wait<0>();
        }
        __syncthreads();

        const float* As = Asb[buf];
        const float* Bs = Bsb[buf];
#pragma unroll
        for (int kk = 0; kk < 4; kk++) {
            wmma::fragment<wmma::matrix_a, 16, 16, 8, wmma::precision::tf32, wmma::row_major> af[4];
            wmma::fragment<wmma::matrix_b, 16, 16, 8, wmma::precision::tf32, wmma::col_major> bf[4];
#pragma unroll
            for (int i = 0; i < 4; i++) {
                wmma::load_matrix_sync(af[i], As + (wr * 64 + i * 16) * GLDA + kk * 8, GLDA);
#pragma unroll
                for (int e = 0; e < af[i].num_elements; e++)
                    af[i].x[e] = wmma::__float_to_tf32(af[i].x[e]);
            }
#pragma unroll
            for (int j = 0; j < 4; j++) {
                wmma::load_matrix_sync(bf[j], Bs + (wc * 64 + j * 16) * GLDA + kk * 8, GLDA);
#pragma unroll
                for (int e = 0; e < bf[j].num_elements; e++)
                    bf[j].x[e] = wmma::__float_to_tf32(bf[j].x[e]);
            }
#pragma unroll
            for (int i = 0; i < 4; i++)
#pragma unroll
                for (int j = 0; j < 4; j++)
                    wmma::mma_sync(acc[i][j], af[i], bf[j], acc[i][j]);
        }
        __syncthreads();
    }

#pragma unroll
    for (int i = 0; i < 4; i++) {
#pragma unroll
        for (int j = 0; j < 4; j++) {
            int row = m0 + wr * 64 + i * 16;
            int col = n0 + wc * 64 + j * 16;
            if (permuted) {
                int b = row >> 11, s = row & 2047;
                int h = col >> 7,  dc = col & 127;
                wmma::store_matrix_sync(
                    out + ((size_t)(b * NHEADS + h) * SEQ + s) * DHEAD + dc,
                    acc[i][j], DHEAD, wmma::mem_row_major);
            } else {
                wmma::store_matrix_sync(out + (size_t)row * EDIM + col,
                                        acc[i][j], EDIM, wmma::mem_row_major);
            }
        }
    }
}

// =================================================================
// Flash attention: per (batch,head), 64-query tile, stream 64-key tiles
// K-bias dropped (cancels in softmax over t); V-bias added in epilogue.
// Double-buffered cp.async K/V pipeline; O accumulated in-place in smem
// via accumulator-fragment load/mma/store; alpha-rescale fused into softmax.
// =================================================================
#define LDQ 132  // 128 + 4 floats; 528B rows (16B aligned)
#define LDS 68   // 64 + 4

#define FQ_OFF   0
#define FK0_OFF  (64 * LDQ)            // 8448
#define FK1_OFF  (2 * 64 * LDQ)
#define FV0_OFF  (3 * 64 * LDQ)
#define FV1_OFF  (4 * 64 * LDQ)
#define FS_OFF   (5 * 64 * LDQ)        // 42240
#define FO_OFF   (FS_OFF + 64 * LDS)   // 46592
#define FL_OFF   (FO_OFF + 64 * LDQ)   // 55040
#define FLASH_SMEM ((FL_OFF + 64) * 4) // 220416 B

__device__ __forceinline__ void flash_load_kv(
    float* Ks, float* Vs, const float* Kg, const float* Vg, int t0, int tid)
{
#pragma unroll
    for (int i = 0; i < 8; i++) {
        int id = tid + i * 256;
        int r = id >> 5, c = (id & 31) << 2;
        cp_async16(Ks + r * LDQ + c, Kg + (size_t)(t0 + r) * DHEAD + c);
    }
#pragma unroll
    for (int i = 0; i < 8; i++) {
        int id = tid + i * 256;
        int r = id >> 5, c = (id & 31) << 2;
        cp_async16(Vs + r * LDQ + c, Vg + (size_t)(t0 + r) * DHEAD + c);
    }
}

__global__ __launch_bounds__(256) void flash_kernel(
    const int* __restrict__ mask,
    const float* __restrict__ bq, const float* __restrict__ bv)
{
    extern __shared__ float sm[];
    float* Qs  = sm + FQ_OFF;
    float* Kb0 = sm + FK0_OFF;
    float* Kb1 = sm + FK1_OFF;
    float* Vb0 = sm + FV0_OFF;
    float* Vb1 = sm + FV1_OFF;
    float* Ss  = sm + FS_OFF;
    float* Os  = sm + FO_OFF;
    float* l_s = sm + FL_OFF;

    const int tid  = threadIdx.x;
    const int warp = tid >> 5;
    const int q0   = blockIdx.x * 64;
    const int nh   = blockIdx.y;
    const int bat  = nh >> 4;
    const int h    = nh & 15;

    const float* Qg = g_q + ((size_t)nh * SEQ + q0) * DHEAD;
    const float* Kg = g_k + (size_t)nh * SEQ * DHEAD;
    const float* Vg = g_v + (size_t)nh * SEQ * DHEAD;

    // prefetch K/V tile 0 (no bias needed — see header comment)
    flash_load_kv(Kb0, Vb0, Kg, Vg, 0, tid);
    cp_commit();

    // Q tile (+bias), zero O accumulator
#pragma unroll
    for (int i = tid; i < 2048; i += 256) {
        int r = i >> 5, c = (i & 31) << 2;
        float4 v = *(const float4*)(Qg + (size_t)r * DHEAD + c);
        float4 b = *(const float4*)(bq + h * DHEAD + c);
        v.x += b.x; v.y += b.y; v.z += b.z; v.w += b.w;
        *(float4*)(Qs + r * LDQ + c) = v;
    }
#pragma unroll
    for (int i = tid; i < 64 * LDQ; i += 256) Os[i] = 0.0f;
    __syncthreads();

    // hoist Q fragments (loaded + tf32-converted once, reused all 32 iters)
    const int rb = warp & 3;   // QK row block (16 rows)
    const int cq = warp >> 2;  // QK col half (32 cols)
    wmma::fragment<wmma::matrix_a, 16, 16, 8, wmma::precision::tf32, wmma::row_major> qf[16];
#pragma unroll
    for (int kk = 0; kk < 16; kk++) {
        wmma::load_matrix_sync(qf[kk], Qs + rb * 16 * LDQ + kk * 8, LDQ);
#pragma unroll
        for (int e = 0; e < qf[kk].num_elements; e++)
            qf[kk].x[e] = wmma::__float_to_tf32(qf[kk].x[e]);
    }

    const int rbp = warp >> 1;  // PV row block
    const int cg  = warp & 1;   // PV col half (64 cols)
    const int q   = tid >> 2;
    const int sub = tid & 3;
    float m_prev = -INFINITY;
    float l_run  = 0.0f;
    const float scale = 0.08838834764831845f;  // 1/sqrt(128)

    for (int it = 0; it < 32; it++) {
        const int t0 = it << 6;
        float* Ks = (it & 1) ? Kb1 : Kb0;
        float* Vs = (it & 1) ? Vb1 : Vb0;

        if (it + 1 < 32) {
            flash_load_kv((it & 1) ? Kb0 : Kb1, (it & 1) ? Vb0 : Vb1,
                          Kg, Vg, t0 + 64, tid);
            cp_commit();
            cp_wait<1>();
        } else {
            cp_wait<0>();
        }
        __syncthreads();

        // mask prefetch into registers (latency hidden behind QK mma)
        int mv[16];
#pragma unroll
        for (int j = 0; j < 16; j++)
            mv[j] = mask[(size_t)(t0 + sub + 4 * j) * SEQ + (q0 + q)];

        // S[q,t] = Q @ K^T   (64x64, K-dim 128)
        {
            wmma::fragment<wmma::accumulator, 16, 16, 8, float> c[2];
            wmma::fill_fragment(c[0], 0.0f);
            wmma::fill_fragment(c[1], 0.0f);
#pragma unroll
            for (int kk = 0; kk < 16; kk++) {
#pragma unroll
                for (int j = 0; j < 2; j++) {
                    wmma::fragment<wmma::matrix_b, 16, 16, 8, wmma::precision::tf32, wmma::col_major> b;
                    wmma::load_matrix_sync(b, Ks + (cq * 32 + j * 16) * LDQ + kk * 8, LDQ);
#pragma unroll
                    for (int e = 0; e < b.num_elements; e++) b.x[e] = wmma::__float_to_tf32(b.x[e]);
                    wmma::mma_sync(c[j], qf[kk], b, c[j]);
                }
            }
#pragma unroll
            for (int j = 0; j < 2; j++)
                wmma::store_matrix_sync(Ss + rb * 16 * LDS + cq * 32 + j * 16, c[j],
                                        LDS, wmma::mem_row_major);
        }
        __syncthreads();

        // online softmax over keys t + fused alpha-rescale of O
        {
            float vals[16];
            float mloc = -INFINITY;
#pragma unroll
            for (int j = 0; j < 16; j++) {
                float v = Ss[q * LDS + sub + 4 * j];
                v = mv[j] ? v * scale : -INFINITY;
                vals[j] = v;
                mloc = fmaxf(mloc, v);
            }
            mloc = fmaxf(mloc, __shfl_xor_sync(0xffffffffu, mloc, 1));
            mloc = fmaxf(mloc, __shfl_xor_sync(0xffffffffu, mloc, 2));
            float m_new = fmaxf(m_prev, mloc);
            float al = (m_prev == -INFINITY) ? 0.0f : __expf(m_prev - m_new);
            float ps = 0.0f;
#pragma unroll
            for (int j = 0; j < 16; j++) {
                float p = (vals[j] == -INFINITY) ? 0.0f : __expf(vals[j] - m_new);
                Ss[q * LDS + sub + 4 * j] = p;
                ps += p;
            }
            ps += __shfl_xor_sync(0xffffffffu, ps, 1);
            ps += __shfl_xor_sync(0xffffffffu, ps, 2);
            l_run = l_run * al + ps;
            m_prev = m_new;
            // rescale this thread's slice of O by alpha (conflict-free stride-4)
#pragma unroll
            for (int u = 0; u < 32; u++) {
                int dv = sub + (u << 2);
                Os[q * LDQ + dv] *= al;
            }
        }
        __syncthreads();

        // O += P[64,64] @ V[64,128]  (accumulate directly into Os)
        {
            wmma::fragment<wmma::accumulator, 16, 16, 8, float> c[4];
#pragma unroll
            for (int j = 0; j < 4; j++)
                wmma::load_matrix_sync(c[j], Os + rbp * 16 * LDQ + cg * 64 + j * 16,
                                       LDQ, wmma::mem_row_major);
#pragma unroll
            for (int kk = 0; kk < 8; kk++) {
                wmma::fragment<wmma::matrix_a, 16, 16, 8, wmma::precision::tf32, wmma::row_major> a;
                wmma::load_matrix_sync(a, Ss + rbp * 16 * LDS + kk * 8, LDS);
#pragma unroll
                for (int e = 0; e < a.num_elements; e++) a.x[e] = wmma::__float_to_tf32(a.x[e]);
#pragma unroll
                for (int j = 0; j < 4; j++) {
                    wmma::fragment<wmma::matrix_b, 16, 16, 8, wmma::precision::tf32, wmma::row_major> b;
                    wmma::load_matrix_sync(b, Vs + kk * 8 * LDQ + cg * 64 + j * 16, LDQ);
#pragma unroll
                    for (int e = 0; e < b.num_elements; e++) b.x[e] = wmma::__float_to_tf32(b.x[e]);
                    wmma::mma_sync(c[j], a, b, c[j]);
                }
            }
#pragma unroll
            for (int j = 0; j < 4; j++)
                wmma::store_matrix_sync(Os + rbp * 16 * LDQ + cg * 64 + j * 16, c[j],
                                        LDQ, wmma::mem_row_major);
        }
        __syncthreads();
    }

    if (sub == 0) l_s[q] = l_run;
    __syncthreads();

    // write O / l + bv to (N,S,E) layout
#pragma unroll
    for (int i = tid; i < 64 * 128; i += 256) {
        int qq = i >> 7, dv = i & 127;
        float l = l_s[qq];
        float o = (l > 0.0f) ? Os[qq * LDQ + dv] / l : 0.0f;
        o += bv[h * DHEAD + dv];
        g_o[((size_t)bat * SEQ + q0 + qq) * EDIM + h * DHEAD + dv] = o;
    }
}

// final bias add
__global__ void bias_add_kernel(float* __restrict__ out, const float* __restrict__ bp)
{
    size_t i = (size_t)blockIdx.x * 256 + threadIdx.x;
    if (i < (size_t)MROWS * EDIM) out[i] += bp[i & (EDIM - 1)];
}

// =================================================================
extern "C" void kernel_launch(void* const* d_in, const int* in_sizes, int n_in,
                              void* d_out, int out_size)
{
    const float* query = (const float*)d_in[0];
    const float* key   = (const float*)d_in[1];
    const float* value = (const float*)d_in[2];
    const int*   mask  = (const int*)d_in[3];
    const float* Wq = (const float*)d_in[4];
    const float* bq = (const float*)d_in[5];
    const float* Wk = (const float*)d_in[6];
    const float* Wv = (const float*)d_in[8];
    const float* bv = (const float*)d_in[9];
    const float* Wp = (const float*)d_in[10];
    const float* bp = (const float*)d_in[11];
    float* out = (float*)d_out;

    float *pq, *pk, *pv, *po;
    cudaGetSymbolAddress((void**)&pq, g_q);
    cudaGetSymbolAddress((void**)&pk, g_k);
    cudaGetSymbolAddress((void**)&pv, g_v);
    cudaGetSymbolAddress((void**)&po, g_o);

    cudaFuncSetAttribute(gemm_at_kernel, cudaFuncAttributeMaxDynamicSharedMemorySize,
                         GEMM_SMEM);
    cudaFuncSetAttribute(flash_kernel, cudaFuncAttributeMaxDynamicSharedMemorySize,
                         FLASH_SMEM);

    dim3 gg(EDIM / 128, MROWS / 128);   // (16, 64)
    gemm_at_kernel<<<gg, 128, GEMM_SMEM>>>(query, Wq, pq, 1);
    gemm_at_kernel<<<gg, 128, GEMM_SMEM>>>(key,   Wk, pk, 1);
    gemm_at_kernel<<<gg, 128, GEMM_SMEM>>>(value, Wv, pv, 1);

    dim3 gf(SEQ / 64, NBATCH * NHEADS);  // (32, 64)
    flash_kernel<<<gf, 256, FLASH_SMEM>>>(mask, bq, bv);

    gemm_at_kernel<<<gg, 128, GEMM_SMEM>>>(po, Wp, out, 0);

    bias_add_kernel<<<(unsigned)(((size_t)MROWS * EDIM + 255) / 256), 256>>>(out, bp);
}

// round 8
// speedup vs baseline: 1.5349x; 1.5349x over previous
#include <cuda_runtime.h>
#include <mma.h>

using namespace nvcuda;

#define EDIM   2048
#define NHEADS 16
#define DHEAD  128
#define NBATCH 4
#define SEQ    2048
#define MROWS  (NBATCH * SEQ)   // 8192

// ---------------- scratch (no allocs allowed) ----------------
__device__ float g_q[16777216];   // (N*H, S, D)
__device__ float g_k[16777216];
__device__ float g_v[16777216];
__device__ float g_o[16777216];   // (N*S, E)

// ---------------- cp.async helpers ----------------
__device__ __forceinline__ void cp_async16(void* smem, const void* gmem) {
    unsigned saddr = (unsigned)__cvta_generic_to_shared(smem);
    asm volatile("cp.async.cg.shared.global [%0], [%1], 16;\n" :: "r"(saddr), "l"(gmem));
}
__device__ __forceinline__ void cp_commit() {
    asm volatile("cp.async.commit_group;\n");
}
template <int N>
__device__ __forceinline__ void cp_wait() {
    asm volatile("cp.async.wait_group %0;\n" :: "n"(N));
}

// =================================================================
// TF32 GEMM:  C[M=8192, N=2048] = A[M,E] @ W[N,E]^T   (no bias)
// 128x128 block tile, BK=32, 8 warps (64x32 warp tile, as R5),
// double-buffered cp.async.  permuted=1 -> (batch, head, s, d) layout
// =================================================================
#define GLDA 40   // 32 + 8 pad (floats); 160B rows, 16B aligned
#define GEMM_SMEM (4 * 128 * GLDA * 4)  // 81920 B

__device__ __forceinline__ void gemm_load_stage(
    float* As, float* Bs, const float* A, const float* W,
    int m0, int n0, int k0, int tid)
{
#pragma unroll
    for (int i = 0; i < 4; i++) {
        int id = tid + i * 256;
        int r = id >> 3, c = (id & 7) << 2;
        cp_async16(As + r * GLDA + c, A + (size_t)(m0 + r) * EDIM + k0 + c);
    }
#pragma unroll
    for (int i = 0; i < 4; i++) {
        int id = tid + i * 256;
        int r = id >> 3, c = (id & 7) << 2;
        cp_async16(Bs + r * GLDA + c, W + (size_t)(n0 + r) * EDIM + k0 + c);
    }
}

__global__ __launch_bounds__(256, 2) void gemm_at_kernel(
    const float* __restrict__ A, const float* __restrict__ W,
    float* __restrict__ out, int permuted)
{
    extern __shared__ float sg[];
    float* Asb[2] = { sg,              sg + 128 * GLDA };
    float* Bsb[2] = { sg + 2*128*GLDA, sg + 3*128*GLDA };

    const int tid  = threadIdx.x;
    const int warp = tid >> 5;
    const int m0 = blockIdx.y * 128;
    const int n0 = blockIdx.x * 128;
    const int wr = warp >> 2;   // 0..1  (row group of 64)
    const int wc = warp & 3;    // 0..3  (col group of 32)

    wmma::fragment<wmma::accumulator, 16, 16, 8, float> acc[4][2];
#pragma unroll
    for (int i = 0; i < 4; i++)
#pragma unroll
        for (int j = 0; j < 2; j++)
            wmma::fill_fragment(acc[i][j], 0.0f);

    gemm_load_stage(Asb[0], Bsb[0], A, W, m0, n0, 0, tid);
    cp_commit();

    for (int k0 = 0; k0 < EDIM; k0 += 32) {
        const int buf = (k0 >> 5) & 1;
        if (k0 + 32 < EDIM) {
            gemm_load_stage(Asb[buf ^ 1], Bsb[buf ^ 1], A, W, m0, n0, k0 + 32, tid);
            cp_commit();
            cp_wait<1>();
        } else {
            cp_wait<0>();
        }
        __syncthreads();

        const float* As = Asb[buf];
        const float* Bs = Bsb[buf];
#pragma unroll
        for (int kk = 0; kk < 4; kk++) {
            wmma::fragment<wmma::matrix_a, 16, 16, 8, wmma::precision::tf32, wmma::row_major> af[4];
            wmma::fragment<wmma::matrix_b, 16, 16, 8, wmma::precision::tf32, wmma::col_major> bf[2];
#pragma unroll
            for (int i = 0; i < 4; i++) {
                wmma::load_matrix_sync(af[i], As + (wr * 64 + i * 16) * GLDA + kk * 8, GLDA);
#pragma unroll
                for (int e = 0; e < af[i].num_elements; e++)
                    af[i].x[e] = wmma::__float_to_tf32(af[i].x[e]);
            }
#pragma unroll
            for (int j = 0; j < 2; j++) {
                wmma::load_matrix_sync(bf[j], Bs + (wc * 32 + j * 16) * GLDA + kk * 8, GLDA);
#pragma unroll
                for (int e = 0; e < bf[j].num_elements; e++)
                    bf[j].x[e] = wmma::__float_to_tf32(bf[j].x[e]);
            }
#pragma unroll
            for (int i = 0; i < 4; i++)
#pragma unroll
                for (int j = 0; j < 2; j++)
                    wmma::mma_sync(acc[i][j], af[i], bf[j], acc[i][j]);
        }
        __syncthreads();
    }

#pragma unroll
    for (int i = 0; i < 4; i++) {
#pragma unroll
        for (int j = 0; j < 2; j++) {
            int row = m0 + wr * 64 + i * 16;
            int col = n0 + wc * 32 + j * 16;
            if (permuted) {
                int b = row >> 11, s = row & 2047;
                int h = col >> 7,  dc = col & 127;
                wmma::store_matrix_sync(
                    out + ((size_t)(b * NHEADS + h) * SEQ + s) * DHEAD + dc,
                    acc[i][j], DHEAD, wmma::mem_row_major);
            } else {
                wmma::store_matrix_sync(out + (size_t)row * EDIM + col,
                                        acc[i][j], EDIM, wmma::mem_row_major);
            }
        }
    }
}

// =================================================================
// Flash attention: per (batch,head), 128-query tile, stream 64-key tiles.
// O held entirely in register accumulator fragments (8 per warp, 16 rows x
// 128 cols). Per-row alpha rescale applied to fragments via a runtime-
// discovered row map. K-bias cancels in softmax; V-bias added in epilogue.
// =================================================================
#define QT  128
#define LDQ 132  // 128 + 4 floats
#define LDS 68   // 64 + 4

#define FQ_OFF   0                      // 128 x LDQ = 16896
#define FK_OFF   (QT * LDQ)             // 64 x LDQ = 8448
#define FV_OFF   (FK_OFF + 64 * LDQ)
#define FS_OFF   (FV_OFF + 64 * LDQ)    // 128 x LDS = 8704
#define FA_OFF   (FS_OFF + QT * LDS)    // alpha 128
#define FL_OFF   (FA_OFF + QT)          // l 128
#define FR_OFF   (FL_OFF + QT)          // rowmat 16x16
#define FLASH_SMEM ((FR_OFF + 256) * 4) // 172032 B

__global__ __launch_bounds__(256) void flash_kernel(
    const int* __restrict__ mask,
    const float* __restrict__ bq, const float* __restrict__ bv)
{
    extern __shared__ float sm[];
    float* Qs   = sm + FQ_OFF;
    float* Ks   = sm + FK_OFF;
    float* Vs   = sm + FV_OFF;
    float* Ss   = sm + FS_OFF;
    float* al_s = sm + FA_OFF;
    float* l_s  = sm + FL_OFF;
    float* rmat = sm + FR_OFF;

    const int tid  = threadIdx.x;
    const int warp = tid >> 5;   // 0..7 -> owns query rows [16*warp, 16*warp+16)
    const int q0   = blockIdx.x * QT;
    const int nh   = blockIdx.y;
    const int bat  = nh >> 4;
    const int h    = nh & 15;

    const float* Qg = g_q + ((size_t)nh * SEQ + q0) * DHEAD;
    const float* Kg = g_k + (size_t)nh * SEQ * DHEAD;
    const float* Vg = g_v + (size_t)nh * SEQ * DHEAD;

    // Q tile (+bias); row-index discovery matrix
#pragma unroll
    for (int i = tid; i < QT * 32; i += 256) {
        int r = i >> 5, c = (i & 31) << 2;
        float4 v = *(const float4*)(Qg + (size_t)r * DHEAD + c);
        float4 b = *(const float4*)(bq + h * DHEAD + c);
        v.x += b.x; v.y += b.y; v.z += b.z; v.w += b.w;
        *(float4*)(Qs + r * LDQ + c) = v;
    }
    if (tid < 256) rmat[tid] = (float)(tid >> 4);
    __syncthreads();

    // discover accumulator element -> row mapping (exact by construction)
    wmma::fragment<wmma::accumulator, 16, 16, 8, float> ridf;
    wmma::load_matrix_sync(ridf, rmat, 16, wmma::mem_row_major);
    int rid[8];
#pragma unroll
    for (int e = 0; e < 8; e++) rid[e] = (int)ridf.x[e];

    // O accumulators: 16 rows x 128 cols per warp
    wmma::fragment<wmma::accumulator, 16, 16, 8, float> of[8];
#pragma unroll
    for (int j = 0; j < 8; j++) wmma::fill_fragment(of[j], 0.0f);

    const int q   = tid >> 1;   // softmax row (0..127)
    const int sub = tid & 1;    // 2 threads per row
    float m_prev = -INFINITY;
    float l_run  = 0.0f;
    const float scale = 0.08838834764831845f;  // 1/sqrt(128)

    for (int it = 0; it < 32; it++) {
        const int t0 = it << 6;
        __syncthreads();  // prev PV done with Vs/Ss

        // load K,V tile (no bias: K-bias cancels, V-bias in epilogue)
#pragma unroll
        for (int i = 0; i < 8; i++) {
            int id = tid + (i << 8);
            int r = id >> 5, c = (id & 31) << 2;
            *(float4*)(Ks + r * LDQ + c) =
                *(const float4*)(Kg + (size_t)(t0 + r) * DHEAD + c);
            *(float4*)(Vs + r * LDQ + c) =
                *(const float4*)(Vg + (size_t)(t0 + r) * DHEAD + c);
        }
        __syncthreads();

        // S[128x64] = Q @ K^T, each warp 16 rows x 64 cols, k-dim 128
        {
            wmma::fragment<wmma::accumulator, 16, 16, 8, float> c[4];
#pragma unroll
            for (int j = 0; j < 4; j++) wmma::fill_fragment(c[j], 0.0f);
#pragma unroll
            for (int kk = 0; kk < 16; kk++) {
                wmma::fragment<wmma::matrix_a, 16, 16, 8, wmma::precision::tf32, wmma::row_major> a;
                wmma::load_matrix_sync(a, Qs + warp * 16 * LDQ + kk * 8, LDQ);
#pragma unroll
                for (int e = 0; e < a.num_elements; e++) a.x[e] = wmma::__float_to_tf32(a.x[e]);
#pragma unroll
                for (int j = 0; j < 4; j++) {
                    wmma::fragment<wmma::matrix_b, 16, 16, 8, wmma::precision::tf32, wmma::col_major> b;
                    wmma::load_matrix_sync(b, Ks + (j * 16) * LDQ + kk * 8, LDQ);
#pragma unroll
                    for (int e = 0; e < b.num_elements; e++) b.x[e] = wmma::__float_to_tf32(b.x[e]);
                    wmma::mma_sync(c[j], a, b, c[j]);
                }
            }
#pragma unroll
            for (int j = 0; j < 4; j++)
                wmma::store_matrix_sync(Ss + warp * 16 * LDS + j * 16, c[j],
                                        LDS, wmma::mem_row_major);
        }
        __syncthreads();

        // online softmax over keys t (2 threads per row, 32 cols each)
        {
            float vals[32];
            float mloc = -INFINITY;
#pragma unroll
            for (int j = 0; j < 32; j++) {
                int t = (j << 1) + sub;
                float v = Ss[q * LDS + t];
                int mv = mask[(size_t)(t0 + t) * SEQ + (q0 + q)];
                v = mv ? v * scale : -INFINITY;
                vals[j] = v;
                mloc = fmaxf(mloc, v);
            }
            mloc = fmaxf(mloc, __shfl_xor_sync(0xffffffffu, mloc, 1));
            float m_new = fmaxf(m_prev, mloc);
            float al = (m_prev == -INFINITY) ? 0.0f : __expf(m_prev - m_new);
            float ps = 0.0f;
#pragma unroll
            for (int j = 0; j < 32; j++) {
                float p = (vals[j] == -INFINITY) ? 0.0f : __expf(vals[j] - m_new);
                Ss[q * LDS + (j << 1) + sub] = p;
                ps += p;
            }
            ps += __shfl_xor_sync(0xffffffffu, ps, 1);
            l_run = l_run * al + ps;
            m_prev = m_new;
            if (sub == 0) al_s[q] = al;
        }
        __syncthreads();

        // O = alpha*O + P @ V   (accumulate in registers)
        {
            float ae[8];
#pragma unroll
            for (int e = 0; e < 8; e++) ae[e] = al_s[warp * 16 + rid[e]];
#pragma unroll
            for (int j = 0; j < 8; j++)
#pragma unroll
                for (int e = 0; e < 8; e++)
                    of[j].x[e] *= ae[e];
#pragma unroll
            for (int kk = 0; kk < 8; kk++) {
                wmma::fragment<wmma::matrix_a, 16, 16, 8, wmma::precision::tf32, wmma::row_major> a;
                wmma::load_matrix_sync(a, Ss + warp * 16 * LDS + kk * 8, LDS);
#pragma unroll
                for (int e = 0; e < a.num_elements; e++) a.x[e] = wmma::__float_to_tf32(a.x[e]);
#pragma unroll
                for (int j = 0; j < 8; j++) {
                    wmma::fragment<wmma::matrix_b, 16, 16, 8, wmma::precision::tf32, wmma::row_major> b;
                    wmma::load_matrix_sync(b, Vs + kk * 8 * LDQ + j * 16, LDQ);
#pragma unroll
                    for (int e = 0; e < b.num_elements; e++) b.x[e] = wmma::__float_to_tf32(b.x[e]);
                    wmma::mma_sync(of[j], a, b, of[j]);
                }
            }
        }
    }

    if (sub == 0) l_s[q] = l_run;
    // dump O fragments into Qs (no longer needed)
    __syncthreads();
#pragma unroll
    for (int j = 0; j < 8; j++)
        wmma::store_matrix_sync(Qs + warp * 16 * LDQ + j * 16, of[j],
                                LDQ, wmma::mem_row_major);
    __syncthreads();

    // epilogue: o = O/l + bv  -> (N,S,E)
#pragma unroll
    for (int i = tid; i < QT * DHEAD; i += 256) {
        int qq = i >> 7, dv = i & 127;
        float l = l_s[qq];
        float o = (l > 0.0f) ? Qs[qq * LDQ + dv] / l : 0.0f;
        o += bv[h * DHEAD + dv];
        g_o[((size_t)bat * SEQ + q0 + qq) * EDIM + h * DHEAD + dv] = o;
    }
}

// final bias add
__global__ void bias_add_kernel(float* __restrict__ out, const float* __restrict__ bp)
{
    size_t i = (size_t)blockIdx.x * 256 + threadIdx.x;
    if (i < (size_t)MROWS * EDIM) out[i] += bp[i & (EDIM - 1)];
}

// =================================================================
extern "C" void kernel_launch(void* const* d_in, const int* in_sizes, int n_in,
                              void* d_out, int out_size)
{
    const float* query = (const float*)d_in[0];
    const float* key   = (const float*)d_in[1];
    const float* value = (const float*)d_in[2];
    const int*   mask  = (const int*)d_in[3];
    const float* Wq = (const float*)d_in[4];
    const float* bq = (const float*)d_in[5];
    const float* Wk = (const float*)d_in[6];
    const float* Wv = (const float*)d_in[8];
    const float* bv = (const float*)d_in[9];
    const float* Wp = (const float*)d_in[10];
    const float* bp = (const float*)d_in[11];
    float* out = (float*)d_out;

    float *pq, *pk, *pv, *po;
    cudaGetSymbolAddress((void**)&pq, g_q);
    cudaGetSymbolAddress((void**)&pk, g_k);
    cudaGetSymbolAddress((void**)&pv, g_v);
    cudaGetSymbolAddress((void**)&po, g_o);

    cudaFuncSetAttribute(gemm_at_kernel, cudaFuncAttributeMaxDynamicSharedMemorySize,
                         GEMM_SMEM);
    cudaFuncSetAttribute(flash_kernel, cudaFuncAttributeMaxDynamicSharedMemorySize,
                         FLASH_SMEM);

    dim3 gg(EDIM / 128, MROWS / 128);   // (16, 64)
    gemm_at_kernel<<<gg, 256, GEMM_SMEM>>>(query, Wq, pq, 1);
    gemm_at_kernel<<<gg, 256, GEMM_SMEM>>>(key,   Wk, pk, 1);
    gemm_at_kernel<<<gg, 256, GEMM_SMEM>>>(value, Wv, pv, 1);

    dim3 gf(SEQ / QT, NBATCH * NHEADS);  // (16, 64)
    flash_kernel<<<gf, 256, FLASH_SMEM>>>(mask, bq, bv);

    gemm_at_kernel<<<gg, 256, GEMM_SMEM>>>(po, Wp, out, 0);

    bias_add_kernel<<<(unsigned)(((size_t)MROWS * EDIM + 255) / 256), 256>>>(out, bp);
}

// round 9
// speedup vs baseline: 1.6421x; 1.0698x over previous
#include <cuda_runtime.h>
#include <mma.h>

using namespace nvcuda;

#define EDIM   2048
#define NHEADS 16
#define DHEAD  128
#define NBATCH 4
#define SEQ    2048
#define MROWS  (NBATCH * SEQ)   // 8192

// ---------------- scratch (no allocs allowed) ----------------
__device__ float g_q[16777216];   // (N*H, S, D)
__device__ float g_k[16777216];
__device__ float g_v[16777216];
__device__ float g_o[16777216];   // (N*S, E)
__device__ unsigned g_mb[SEQ * (SEQ / 32)];  // bitmask: [s][t/32], bit t%32

// ---------------- cp.async helpers ----------------
__device__ __forceinline__ void cp_async16(void* smem, const void* gmem) {
    unsigned saddr = (unsigned)__cvta_generic_to_shared(smem);
    asm volatile("cp.async.cg.shared.global [%0], [%1], 16;\n" :: "r"(saddr), "l"(gmem));
}
__device__ __forceinline__ void cp_commit() {
    asm volatile("cp.async.commit_group;\n");
}
template <int N>
__device__ __forceinline__ void cp_wait() {
    asm volatile("cp.async.wait_group %0;\n" :: "n"(N));
}

// =================================================================
// mask -> bitmask  (mb[s][w] bit b = mask[32w+b][s] != 0)
// =================================================================
__global__ void mask_bits_kernel(const int* __restrict__ mask)
{
    int s = blockIdx.x * 256 + threadIdx.x;
    int w = blockIdx.y;
    unsigned bits = 0;
#pragma unroll
    for (int b = 0; b < 32; b++)
        bits |= (mask[(size_t)(w * 32 + b) * SEQ + s] != 0 ? 1u : 0u) << b;
    g_mb[(size_t)s * (SEQ / 32) + w] = bits;
}

// =================================================================
// TF32 GEMM:  C[M=8192, N=2048] = A[M,E] @ W[N,E]^T   (no bias)
// 128x128 block tile, BK=32, 8 warps (64x32 warp tile),
// 3-stage cp.async pipeline, 1 sync per K-step.
// permuted=1 -> (batch, head, s, d) layout
// =================================================================
#define GLDA 36   // 32 + 4 pad; 144B rows (16B aligned)
#define GTILE (128 * GLDA)
#define GEMM_SMEM (6 * GTILE * 4)   // 110592 B

__device__ __forceinline__ void gemm_load_stage(
    float* As, float* Bs, const float* A, const float* W,
    int m0, int n0, int k0, int tid)
{
#pragma unroll
    for (int i = 0; i < 4; i++) {
        int id = tid + i * 256;
        int r = id >> 3, c = (id & 7) << 2;
        cp_async16(As + r * GLDA + c, A + (size_t)(m0 + r) * EDIM + k0 + c);
    }
#pragma unroll
    for (int i = 0; i < 4; i++) {
        int id = tid + i * 256;
        int r = id >> 3, c = (id & 7) << 2;
        cp_async16(Bs + r * GLDA + c, W + (size_t)(n0 + r) * EDIM + k0 + c);
    }
}

__global__ __launch_bounds__(256, 2) void gemm_at_kernel(
    const float* __restrict__ A, const float* __restrict__ W,
    float* __restrict__ out, int permuted)
{
    extern __shared__ float sg[];
    float* Asl[3] = { sg,             sg + 2 * GTILE, sg + 4 * GTILE };
    float* Bsl[3] = { sg + GTILE,     sg + 3 * GTILE, sg + 5 * GTILE };

    const int tid  = threadIdx.x;
    const int warp = tid >> 5;
    const int m0 = blockIdx.y * 128;
    const int n0 = blockIdx.x * 128;
    const int wr = warp >> 2;   // 0..1  (row group of 64)
    const int wc = warp & 3;    // 0..3  (col group of 32)

    wmma::fragment<wmma::accumulator, 16, 16, 8, float> acc[4][2];
#pragma unroll
    for (int i = 0; i < 4; i++)
#pragma unroll
        for (int j = 0; j < 2; j++)
            wmma::fill_fragment(acc[i][j], 0.0f);

    gemm_load_stage(Asl[0], Bsl[0], A, W, m0, n0, 0, tid);
    cp_commit();
    gemm_load_stage(Asl[1], Bsl[1], A, W, m0, n0, 32, tid);
    cp_commit();

    const int NIT = EDIM / 32;   // 64
    for (int i = 0; i < NIT; i++) {
        if (i < NIT - 1) cp_wait<1>(); else cp_wait<0>();
        __syncthreads();
        if (i + 2 < NIT) {
            gemm_load_stage(Asl[(i + 2) % 3], Bsl[(i + 2) % 3],
                            A, W, m0, n0, (i + 2) * 32, tid);
            cp_commit();
        }

        const float* As = Asl[i % 3];
        const float* Bs = Bsl[i % 3];
#pragma unroll
        for (int kk = 0; kk < 4; kk++) {
            wmma::fragment<wmma::matrix_a, 16, 16, 8, wmma::precision::tf32, wmma::row_major> af[4];
            wmma::fragment<wmma::matrix_b, 16, 16, 8, wmma::precision::tf32, wmma::col_major> bf[2];
#pragma unroll
            for (int ii = 0; ii < 4; ii++) {
                wmma::load_matrix_sync(af[ii], As + (wr * 64 + ii * 16) * GLDA + kk * 8, GLDA);
#pragma unroll
                for (int e = 0; e < af[ii].num_elements; e++)
                    af[ii].x[e] = wmma::__float_to_tf32(af[ii].x[e]);
            }
#pragma unroll
            for (int j = 0; j < 2; j++) {
                wmma::load_matrix_sync(bf[j], Bs + (wc * 32 + j * 16) * GLDA + kk * 8, GLDA);
#pragma unroll
                for (int e = 0; e < bf[j].num_elements; e++)
                    bf[j].x[e] = wmma::__float_to_tf32(bf[j].x[e]);
            }
#pragma unroll
            for (int ii = 0; ii < 4; ii++)
#pragma unroll
                for (int j = 0; j < 2; j++)
                    wmma::mma_sync(acc[ii][j], af[ii], bf[j], acc[ii][j]);
        }
    }
    __syncthreads();

#pragma unroll
    for (int i = 0; i < 4; i++) {
#pragma unroll
        for (int j = 0; j < 2; j++) {
            int row = m0 + wr * 64 + i * 16;
            int col = n0 + wc * 32 + j * 16;
            if (permuted) {
                int b = row >> 11, s = row & 2047;
                int h = col >> 7,  dc = col & 127;
                wmma::store_matrix_sync(
                    out + ((size_t)(b * NHEADS + h) * SEQ + s) * DHEAD + dc,
                    acc[i][j], DHEAD, wmma::mem_row_major);
            } else {
                wmma::store_matrix_sync(out + (size_t)row * EDIM + col,
                                        acc[i][j], EDIM, wmma::mem_row_major);
            }
        }
    }
}

// =================================================================
// Flash attention: per (batch,head), 128-query tile, 64-key tiles.
// O in register fragments. cp.async: K single-buffer (reload after QK),
// V double-buffer, loads overlap softmax+PV. Q & P pre-converted to tf32
// in smem (no a-fragment CVTs). Bitmask for mask. K-bias cancels in
// softmax; V-bias in epilogue.
// =================================================================
#define QT  128
#define LDQ 132  // 128 + 4 floats
#define LDS 68   // 64 + 4

#define FQ_OFF   0                      // 128 x LDQ
#define FK_OFF   (QT * LDQ)             // 64 x LDQ
#define FV0_OFF  (FK_OFF + 64 * LDQ)
#define FV1_OFF  (FV0_OFF + 64 * LDQ)
#define FS_OFF   (FV1_OFF + 64 * LDQ)   // 128 x LDS
#define FA_OFF   (FS_OFF + QT * LDS)
#define FL_OFF   (FA_OFF + QT)
#define FR_OFF   (FL_OFF + QT)
#define FLASH_SMEM ((FR_OFF + 256) * 4) // 205824 B

__global__ __launch_bounds__(256) void flash_kernel(
    const float* __restrict__ bq, const float* __restrict__ bv)
{
    extern __shared__ float sm[];
    float* Qs   = sm + FQ_OFF;
    float* Ks   = sm + FK_OFF;
    float* Vb[2] = { sm + FV0_OFF, sm + FV1_OFF };
    float* Ss   = sm + FS_OFF;
    float* al_s = sm + FA_OFF;
    float* l_s  = sm + FL_OFF;
    float* rmat = sm + FR_OFF;

    const int tid  = threadIdx.x;
    const int warp = tid >> 5;
    const int q0   = blockIdx.x * QT;
    const int nh   = blockIdx.y;
    const int bat  = nh >> 4;
    const int h    = nh & 15;

    const float* Qg = g_q + ((size_t)nh * SEQ + q0) * DHEAD;
    const float* Kg = g_k + (size_t)nh * SEQ * DHEAD;
    const float* Vg = g_v + (size_t)nh * SEQ * DHEAD;

    // prefetch K0/V0
#pragma unroll
    for (int i = 0; i < 8; i++) {
        int id = tid + (i << 8);
        int r = id >> 5, c = (id & 31) << 2;
        cp_async16(Ks + r * LDQ + c,    Kg + (size_t)r * DHEAD + c);
        cp_async16(Vb[0] + r * LDQ + c, Vg + (size_t)r * DHEAD + c);
    }
    cp_commit();

    // Q tile (+bias), pre-converted to tf32; row-index discovery matrix
#pragma unroll
    for (int i = tid; i < QT * 32; i += 256) {
        int r = i >> 5, c = (i & 31) << 2;
        float4 v = *(const float4*)(Qg + (size_t)r * DHEAD + c);
        float4 b = *(const float4*)(bq + h * DHEAD + c);
        v.x = wmma::__float_to_tf32(v.x + b.x);
        v.y = wmma::__float_to_tf32(v.y + b.y);
        v.z = wmma::__float_to_tf32(v.z + b.z);
        v.w = wmma::__float_to_tf32(v.w + b.w);
        *(float4*)(Qs + r * LDQ + c) = v;
    }
    rmat[tid] = (float)(tid >> 4);
    __syncthreads();

    wmma::fragment<wmma::accumulator, 16, 16, 8, float> ridf;
    wmma::load_matrix_sync(ridf, rmat, 16, wmma::mem_row_major);
    int rid[8];
#pragma unroll
    for (int e = 0; e < 8; e++) rid[e] = (int)ridf.x[e];

    // O accumulators: 32 rows x 64 cols per warp (2 frag-rows x 4 frag-cols)
    const int wr2 = warp >> 1;   // 0..3 : 32-row group
    const int wc2 = warp & 1;    // 0..1 : QK 32-col group / PV 64-col group
    wmma::fragment<wmma::accumulator, 16, 16, 8, float> of[2][4];
#pragma unroll
    for (int fr = 0; fr < 2; fr++)
#pragma unroll
        for (int j = 0; j < 4; j++) wmma::fill_fragment(of[fr][j], 0.0f);

    const int q   = tid >> 1;   // softmax row (0..127)
    const int sub = tid & 1;    // 2 threads per row
    const unsigned* mbrow = g_mb + (size_t)(q0 + q) * (SEQ / 32);
    float m_prev = -INFINITY;
    float l_run  = 0.0f;
    const float scale = 0.08838834764831845f;  // 1/sqrt(128)

    for (int it = 0; it < 32; it++) {
        const int t0 = it << 6;
        cp_wait<0>();
        __syncthreads();   // K/V arrived; prev PV done with Ss/Vb

        // S[128x64] = Q @ K^T, warp tile 32x32
        {
            wmma::fragment<wmma::accumulator, 16, 16, 8, float> c[2][2];
#pragma unroll
            for (int ii = 0; ii < 2; ii++)
#pragma unroll
                for (int j = 0; j < 2; j++) wmma::fill_fragment(c[ii][j], 0.0f);
#pragma unroll
            for (int kk = 0; kk < 16; kk++) {
                wmma::fragment<wmma::matrix_a, 16, 16, 8, wmma::precision::tf32, wmma::row_major> a[2];
                wmma::fragment<wmma::matrix_b, 16, 16, 8, wmma::precision::tf32, wmma::col_major> b[2];
#pragma unroll
                for (int ii = 0; ii < 2; ii++)
                    wmma::load_matrix_sync(a[ii], Qs + (wr2 * 32 + ii * 16) * LDQ + kk * 8, LDQ);
#pragma unroll
                for (int j = 0; j < 2; j++) {
                    wmma::load_matrix_sync(b[j], Ks + (wc2 * 32 + j * 16) * LDQ + kk * 8, LDQ);
#pragma unroll
                    for (int e = 0; e < b[j].num_elements; e++)
                        b[j].x[e] = wmma::__float_to_tf32(b[j].x[e]);
                }
#pragma unroll
                for (int ii = 0; ii < 2; ii++)
#pragma unroll
                    for (int j = 0; j < 2; j++)
                        wmma::mma_sync(c[ii][j], a[ii], b[j], c[ii][j]);
            }
#pragma unroll
            for (int ii = 0; ii < 2; ii++)
#pragma unroll
                for (int j = 0; j < 2; j++)
                    wmma::store_matrix_sync(Ss + (wr2 * 32 + ii * 16) * LDS + wc2 * 32 + j * 16,
                                            c[ii][j], LDS, wmma::mem_row_major);
        }
        __syncthreads();

        // prefetch next K/V (overlaps softmax + PV)
        if (it + 1 < 32) {
            float* Vn = Vb[(it + 1) & 1];
#pragma unroll
            for (int i = 0; i < 8; i++) {
                int id = tid + (i << 8);
                int r = id >> 5, c = (id & 31) << 2;
                cp_async16(Ks + r * LDQ + c, Kg + (size_t)(t0 + 64 + r) * DHEAD + c);
                cp_async16(Vn + r * LDQ + c, Vg + (size_t)(t0 + 64 + r) * DHEAD + c);
            }
            cp_commit();
        }

        // online softmax over keys t (2 threads/row, 32 cols each); bitmask
        {
            unsigned w0 = mbrow[(t0 >> 5)];
            unsigned w1 = mbrow[(t0 >> 5) + 1];
            float vals[32];
            float mloc = -INFINITY;
            if ((w0 & w1) == 0xffffffffu) {
#pragma unroll
                for (int j = 0; j < 32; j++) {
                    float v = Ss[q * LDS + (j << 1) + sub] * scale;
                    vals[j] = v;
                    mloc = fmaxf(mloc, v);
                }
            } else {
#pragma unroll
                for (int j = 0; j < 32; j++) {
                    int t = (j << 1) + sub;
                    unsigned wb = (t < 32) ? w0 : w1;
                    int mv = (wb >> (t & 31)) & 1;
                    float v = Ss[q * LDS + t];
                    v = mv ? v * scale : -INFINITY;
                    vals[j] = v;
                    mloc = fmaxf(mloc, v);
                }
            }
            mloc = fmaxf(mloc, __shfl_xor_sync(0xffffffffu, mloc, 1));
            float m_new = fmaxf(m_prev, mloc);
            float al = (m_prev == -INFINITY) ? 0.0f : __expf(m_prev - m_new);
            float ps = 0.0f;
#pragma unroll
            for (int j = 0; j < 32; j++) {
                float p = (vals[j] == -INFINITY) ? 0.0f : __expf(vals[j] - m_new);
                Ss[q * LDS + (j << 1) + sub] = wmma::__float_to_tf32(p);
                ps += p;
            }
            ps += __shfl_xor_sync(0xffffffffu, ps, 1);
            l_run = l_run * al + ps;
            m_prev = m_new;
            if (sub == 0) al_s[q] = al;
        }
        __syncthreads();

        // O = alpha*O + P @ V, warp tile 32x64
        {
            const float* Vs = Vb[it & 1];
            float ae[2][8];
#pragma unroll
            for (int e = 0; e < 8; e++) {
                ae[0][e] = al_s[wr2 * 32 + rid[e]];
                ae[1][e] = al_s[wr2 * 32 + 16 + rid[e]];
            }
#pragma unroll
            for (int fr = 0; fr < 2; fr++)
#pragma unroll
                for (int j = 0; j < 4; j++)
#pragma unroll
                    for (int e = 0; e < 8; e++)
                        of[fr][j].x[e] *= ae[fr][e];
#pragma unroll
            for (int kk = 0; kk < 8; kk++) {
                wmma::fragment<wmma::matrix_a, 16, 16, 8, wmma::precision::tf32, wmma::row_major> a[2];
                wmma::fragment<wmma::matrix_b, 16, 16, 8, wmma::precision::tf32, wmma::row_major> b[4];
#pragma unroll
                for (int fr = 0; fr < 2; fr++)
                    wmma::load_matrix_sync(a[fr], Ss + (wr2 * 32 + fr * 16) * LDS + kk * 8, LDS);
#pragma unroll
                for (int j = 0; j < 4; j++) {
                    wmma::load_matrix_sync(b[j], Vs + kk * 8 * LDQ + wc2 * 64 + j * 16, LDQ);
#pragma unroll
                    for (int e = 0; e < b[j].num_elements; e++)
                        b[j].x[e] = wmma::__float_to_tf32(b[j].x[e]);
                }
#pragma unroll
                for (int fr = 0; fr < 2; fr++)
#pragma unroll
                    for (int j = 0; j < 4; j++)
                        wmma::mma_sync(of[fr][j], a[fr], b[j], of[fr][j]);
            }
        }
    }

    if (sub == 0) l_s[q] = l_run;
    __syncthreads();
#pragma unroll
    for (int fr = 0; fr < 2; fr++)
#pragma unroll
        for (int j = 0; j < 4; j++)
            wmma::store_matrix_sync(Qs + (wr2 * 32 + fr * 16) * LDQ + wc2 * 64 + j * 16,
                                    of[fr][j], LDQ, wmma::mem_row_major);
    __syncthreads();

    // epilogue: o = O/l + bv  -> (N,S,E)
#pragma unroll
    for (int i = tid; i < QT * DHEAD; i += 256) {
        int qq = i >> 7, dv = i & 127;
        float l = l_s[qq];
        float o = (l > 0.0f) ? Qs[qq * LDQ + dv] / l : 0.0f;
        o += bv[h * DHEAD + dv];
        g_o[((size_t)bat * SEQ + q0 + qq) * EDIM + h * DHEAD + dv] = o;
    }
}

// final bias add
__global__ void bias_add_kernel(float* __restrict__ out, const float* __restrict__ bp)
{
    size_t i = (size_t)blockIdx.x * 256 + threadIdx.x;
    if (i < (size_t)MROWS * EDIM) out[i] += bp[i & (EDIM - 1)];
}

// =================================================================
extern "C" void kernel_launch(void* const* d_in, const int* in_sizes, int n_in,
                              void* d_out, int out_size)
{
    const float* query = (const float*)d_in[0];
    const float* key   = (const float*)d_in[1];
    const float* value = (const float*)d_in[2];
    const int*   mask  = (const int*)d_in[3];
    const float* Wq = (const float*)d_in[4];
    const float* bq = (const float*)d_in[5];
    const float* Wk = (const float*)d_in[6];
    const float* Wv = (const float*)d_in[8];
    const float* bv = (const float*)d_in[9];
    const float* Wp = (const float*)d_in[10];
    const float* bp = (const float*)d_in[11];
    float* out = (float*)d_out;

    float *pq, *pk, *pv, *po;
    cudaGetSymbolAddress((void**)&pq, g_q);
    cudaGetSymbolAddress((void**)&pk, g_k);
    cudaGetSymbolAddress((void**)&pv, g_v);
    cudaGetSymbolAddress((void**)&po, g_o);

    cudaFuncSetAttribute(gemm_at_kernel, cudaFuncAttributeMaxDynamicSharedMemorySize,
                         GEMM_SMEM);
    cudaFuncSetAttribute(flash_kernel, cudaFuncAttributeMaxDynamicSharedMemorySize,
                         FLASH_SMEM);

    dim3 gm(SEQ / 256, SEQ / 32);  // (8, 64)
    mask_bits_kernel<<<gm, 256>>>(mask);

    dim3 gg(EDIM / 128, MROWS / 128);   // (16, 64)
    gemm_at_kernel<<<gg, 256, GEMM_SMEM>>>(query, Wq, pq, 1);
    gemm_at_kernel<<<gg, 256, GEMM_SMEM>>>(key,   Wk, pk, 1);
    gemm_at_kernel<<<gg, 256, GEMM_SMEM>>>(value, Wv, pv, 1);

    dim3 gf(SEQ / QT, NBATCH * NHEADS);  // (16, 64)
    flash_kernel<<<gf, 256, FLASH_SMEM>>>(bq, bv);

    gemm_at_kernel<<<gg, 256, GEMM_SMEM>>>(po, Wp, out, 0);

    bias_add_kernel<<<(unsigned)(((size_t)MROWS * EDIM + 255) / 256), 256>>>(out, bp);
}